// round 17
// baseline (speedup 1.0000x reference)
#include <cuda_runtime.h>
#include <cuda_fp16.h>
#include <cstdint>
#include <math.h>

#define EPS 1e-5f

// ---------------- scratch (device globals) ----------------
__device__ float g_bufA[67108864];               // GEMM1 H outputs (max 131072x512, fp32)
__device__ __half g_b16[16777216];               // GEMM2 fp16 outputs (max 32768x512)
__device__ __half g_f0h[33554432];               // f0 fp16
__device__ __half g_f1h[16777216];               // f1 fp16
__device__ __half g_f2h[8388608];                // f2 fp16
__device__ __half g_wh[4194304];                 // weight fp16 planes (all 8 GEMMs)
__device__ float g_sum[1024];
__device__ float g_sumsq[1024];
__device__ float g_scale[1024];
__device__ float g_shift[1024];

// ---------------- PTX helpers ----------------
__device__ __forceinline__ uint32_t smem_u32(const void* p) {
    uint32_t a;
    asm("{ .reg .u64 t; cvta.to.shared.u64 t, %1; cvt.u32.u64 %0, t; }" : "=r"(a) : "l"(p));
    return a;
}
__device__ __forceinline__ void cp16(uint32_t sdst, const void* gsrc) {
    asm volatile("cp.async.cg.shared.global [%0], [%1], 16;" :: "r"(sdst), "l"(gsrc));
}
#define CP_COMMIT() asm volatile("cp.async.commit_group;" ::: "memory")
#define CP_WAIT(n)  asm volatile("cp.async.wait_group %0;" :: "n"(n) : "memory")

__device__ __forceinline__ void ldsm_x4(uint32_t* r, uint32_t addr) {
    asm volatile("ldmatrix.sync.aligned.m8n8.x4.shared.b16 {%0,%1,%2,%3}, [%4];"
                 : "=r"(r[0]), "=r"(r[1]), "=r"(r[2]), "=r"(r[3]) : "r"(addr));
}
__device__ __forceinline__ void ldsm_x4_t(uint32_t* r, uint32_t addr) {
    asm volatile("ldmatrix.sync.aligned.m8n8.x4.trans.shared.b16 {%0,%1,%2,%3}, [%4];"
                 : "=r"(r[0]), "=r"(r[1]), "=r"(r[2]), "=r"(r[3]) : "r"(addr));
}
__device__ __forceinline__ void mma16816(float* d, const uint32_t* a, uint32_t b0, uint32_t b1) {
    asm volatile("mma.sync.aligned.m16n8k16.row.col.f32.f16.f16.f32 "
                 "{%0,%1,%2,%3}, {%4,%5,%6,%7}, {%8,%9}, {%0,%1,%2,%3};"
                 : "+f"(d[0]), "+f"(d[1]), "+f"(d[2]), "+f"(d[3])
                 : "r"(a[0]), "r"(a[1]), "r"(a[2]), "r"(a[3]), "r"(b0), "r"(b1));
}

// fp32x4 -> fp16x4 (8B)
__device__ __forceinline__ void cvt4h(float4 v, char* p) {
    __half2 h01 = __floats2half2_rn(v.x, v.y);
    __half2 h23 = __floats2half2_rn(v.z, v.w);
    uint2 u;
    u.x = *reinterpret_cast<uint32_t*>(&h01);
    u.y = *reinterpret_cast<uint32_t*>(&h23);
    *reinterpret_cast<uint2*>(p) = u;
}

// ---------------- elementwise kernels ----------------
__global__ void zero_stats_kernel(int n) {
    int i = blockIdx.x * blockDim.x + threadIdx.x;
    if (i < n) { g_sum[i] = 0.f; g_sumsq[i] = 0.f; }
}

__global__ void finalize_stats_kernel(const float* __restrict__ gamma,
                                      const float* __restrict__ beta,
                                      int N, float invM) {
    int i = blockIdx.x * blockDim.x + threadIdx.x;
    if (i >= N) return;
    float mu  = g_sum[i] * invM;
    float var = g_sumsq[i] * invM - mu * mu;
    float sc  = gamma[i] * rsqrtf(var + EPS);
    g_scale[i] = sc;
    g_shift[i] = beta[i] - mu * sc;
}

// fp32 -> fp16 plane, same layout (weights or activations)
__global__ void cvt_kernel(const float* __restrict__ W,
                           __half* __restrict__ hp, long long total4) {
    for (long long i = (long long)blockIdx.x * blockDim.x + threadIdx.x;
         i < total4; i += (long long)gridDim.x * blockDim.x) {
        float4 v = *(const float4*)(W + i * 4);
        cvt4h(v, (char*)(hp + i * 4));
    }
}

// ---------------- gemm16: GEMM1 kernel (fp16 A, 4-stage single-sync pipeline) ----------------
template <bool CAT>
__global__ __launch_bounds__(256, 2)
void gemm16_kernel(const __half* __restrict__ Aleft, const __half* __restrict__ Aright,
                   const int* __restrict__ gidx, int outRPB, int srcRPB,
                   const __half* __restrict__ Wh,
                   const float* __restrict__ bias, float* __restrict__ C,
                   int M, int N, int K) {
    constexpr int A_STR = 80;
    constexpr int W_STR = 272;
    constexpr int A_PLANE = 128 * A_STR;      // 10240
    constexpr int W_PLANE = 32 * W_STR;       // 8704
    constexpr int OFF_A = 0;
    constexpr int OFF_W = A_PLANE;
    constexpr int STAGE = A_PLANE + W_PLANE;  // 18944
    constexpr int S = 4;

    extern __shared__ char sm[];
    const uint32_t smb = smem_u32(sm);

    const int tid = threadIdx.x;
    const int wid = tid >> 5;
    const int lane = tid & 31;
    const int warp_m = (wid >> 2) * 64;
    const int warp_n = (wid & 3) * 32;
    const int bm0 = blockIdx.y * 128;
    const int bn0 = blockIdx.x * 128;
    const int T = K >> 5;
    const int Cl = K >> 1;

    int aKc[2];
    uint32_t aS[2];
    int offL[2], offR[2];
#pragma unroll
    for (int i = 0; i < 2; i++) {
        int c = tid + (i << 8);
        int arow = c >> 2;
        aKc[i] = (c & 3) * 8;
        aS[i] = arow * A_STR + (c & 3) * 16;
        int r = bm0 + arow;
        if (CAT) {
            int b = r / outRPB;
            int src = b * srcRPB + gidx[r];
            offL[i] = r * Cl;
            offR[i] = src * Cl;
        } else {
            offL[i] = r * K;
            offR[i] = 0;
        }
    }
    int wRow[2], wCol[2];
    uint32_t wS[2];
#pragma unroll
    for (int i = 0; i < 2; i++) {
        int c = tid + (i << 8);
        wRow[i] = c >> 4;
        wCol[i] = (c & 15) * 8;
        wS[i] = wRow[i] * W_STR + (c & 15) * 16;
    }

    uint32_t a_off[4], b_off[2];
#pragma unroll
    for (int mt = 0; mt < 4; mt++)
        a_off[mt] = (uint32_t)((warp_m + mt * 16 + (lane & 15)) * A_STR + ((lane >> 4) << 3) * 2);
#pragma unroll
    for (int np = 0; np < 2; np++)
        b_off[np] = (uint32_t)((lane & 15) * W_STR + (warp_n + np * 16 + ((lane >> 4) << 3)) * 2);

    float acc[4][4][4];
#pragma unroll
    for (int mt = 0; mt < 4; mt++)
#pragma unroll
        for (int nt = 0; nt < 4; nt++)
#pragma unroll
            for (int q = 0; q < 4; q++) acc[mt][nt][q] = 0.f;

    auto issue_stage = [&](int t, uint32_t sb) {
        const int k0 = t << 5;
#pragma unroll
        for (int i = 0; i < 2; i++) {
            int col = k0 + aKc[i];
            const __half* src;
            if (CAT)
                src = (col < Cl) ? (Aleft + offL[i] + col) : (Aright + offR[i] + (col - Cl));
            else
                src = Aleft + offL[i] + col;
            cp16(sb + OFF_A + aS[i], src);
        }
#pragma unroll
        for (int i = 0; i < 2; i++) {
            size_t gw = (size_t)(k0 + wRow[i]) * N + bn0 + wCol[i];
            cp16(sb + OFF_W + wS[i], Wh + gw);
        }
    };

#pragma unroll
    for (int p = 0; p < S - 1; p++) {
        if (p < T) issue_stage(p, smb + p * STAGE);
        CP_COMMIT();
    }

    for (int t = 0; t < T; t++) {
        CP_WAIT(2);
        __syncthreads();
        if (t + S - 1 < T) issue_stage(t + S - 1, smb + ((t + S - 1) & (S - 1)) * STAGE);
        CP_COMMIT();

        const uint32_t sbase = smb + (t & (S - 1)) * STAGE;
#pragma unroll
        for (int ks = 0; ks < 2; ks++) {
            uint32_t ah[4][4];
#pragma unroll
            for (int mt = 0; mt < 4; mt++)
                ldsm_x4(ah[mt], sbase + OFF_A + a_off[mt] + ks * 32);
#pragma unroll
            for (int np = 0; np < 2; np++) {
                uint32_t bh[4];
                ldsm_x4_t(bh, sbase + OFF_W + b_off[np] + ks * (16 * W_STR));
#pragma unroll
                for (int mt = 0; mt < 4; mt++)
#pragma unroll
                    for (int half = 0; half < 2; half++)
                        mma16816(acc[mt][np * 2 + half], ah[mt], bh[half * 2], bh[half * 2 + 1]);
            }
        }
    }

#pragma unroll
    for (int nt = 0; nt < 4; nt++) {
        int c0 = bn0 + warp_n + (nt >> 1) * 16 + (nt & 1) * 8 + (lane & 3) * 2;
        float b0 = bias[c0], b1 = bias[c0 + 1];
        float s0 = 0.f, s1 = 0.f, q0 = 0.f, q1 = 0.f;
#pragma unroll
        for (int mt = 0; mt < 4; mt++) {
            int r0 = bm0 + warp_m + mt * 16 + (lane >> 2);
            float v0 = acc[mt][nt][0] + b0, v1 = acc[mt][nt][1] + b1;
            float v2 = acc[mt][nt][2] + b0, v3 = acc[mt][nt][3] + b1;
            float2 p0; p0.x = v0; p0.y = v1;
            float2 p1; p1.x = v2; p1.y = v3;
            *(float2*)(C + (size_t)r0 * N + c0) = p0;
            *(float2*)(C + (size_t)(r0 + 8) * N + c0) = p1;
            s0 += v0 + v2; s1 += v1 + v3;
            q0 += v0 * v0 + v2 * v2; q1 += v1 * v1 + v3 * v3;
        }
#pragma unroll
        for (int off = 4; off < 32; off <<= 1) {
            s0 += __shfl_xor_sync(0xFFFFFFFFu, s0, off);
            s1 += __shfl_xor_sync(0xFFFFFFFFu, s1, off);
            q0 += __shfl_xor_sync(0xFFFFFFFFu, q0, off);
            q1 += __shfl_xor_sync(0xFFFFFFFFu, q1, off);
        }
        if ((lane >> 2) == 0) {
            atomicAdd(&g_sum[c0], s0);
            atomicAdd(&g_sum[c0 + 1], s1);
            atomicAdd(&g_sumsq[c0], q0);
            atomicAdd(&g_sumsq[c0 + 1], q1);
        }
    }
}

// ---------------- gemm32: GEMM2 kernel (fp32 A + BN norm + ReLU), overlapped W ring ----------------
// A 2-slot smem ring (STS by compute warps), W 3-slot cp.async ring, 1 barrier/K-step.
template <bool OUT16>
__global__ __launch_bounds__(256, 2)
void gemm32_kernel(const float* __restrict__ A,
                   const __half* __restrict__ Wh,
                   const float* __restrict__ bias, void* __restrict__ Cout,
                   int M, int N, int K) {
    constexpr int A_STR = 80;
    constexpr int W_STR = 272;
    constexpr int A_PLANE = 128 * A_STR;   // 10240
    constexpr int W_PLANE = 32 * W_STR;    // 8704
    constexpr int OFF_W = 2 * A_PLANE;     // W slots after 2 A slots

    extern __shared__ char sm[];
    const uint32_t smb = smem_u32(sm);

    const int tid = threadIdx.x;
    const int wid = tid >> 5;
    const int lane = tid & 31;
    const int warp_m = (wid >> 2) * 64;
    const int warp_n = (wid & 3) * 32;
    const int bm0 = blockIdx.y * 128;
    const int bn0 = blockIdx.x * 128;
    const int T = K >> 5;

    int a_row[4], a_c[4];
    uint32_t a_soff[4];
#pragma unroll
    for (int i = 0; i < 4; i++) {
        int idx = tid + (i << 8);
        a_row[i] = idx >> 3;
        a_c[i] = (idx & 7) << 2;
        a_soff[i] = a_row[i] * A_STR + a_c[i] * 2;
    }
    int wRow[2], wCol[2];
    uint32_t wS[2];
#pragma unroll
    for (int i = 0; i < 2; i++) {
        int c = tid + (i << 8);
        wRow[i] = c >> 4;
        wCol[i] = (c & 15) * 8;
        wS[i] = wRow[i] * W_STR + (c & 15) * 16;
    }

    uint32_t a_off[4], b_off[2];
#pragma unroll
    for (int mt = 0; mt < 4; mt++)
        a_off[mt] = (uint32_t)((warp_m + mt * 16 + (lane & 15)) * A_STR + ((lane >> 4) << 3) * 2);
#pragma unroll
    for (int np = 0; np < 2; np++)
        b_off[np] = (uint32_t)((lane & 15) * W_STR + (warp_n + np * 16 + ((lane >> 4) << 3)) * 2);

    float acc[4][4][4];
#pragma unroll
    for (int mt = 0; mt < 4; mt++)
#pragma unroll
        for (int nt = 0; nt < 4; nt++)
#pragma unroll
            for (int q = 0; q < 4; q++) acc[mt][nt][q] = 0.f;

    auto issueW = [&](int t, int slot) {
        const int k0 = t << 5;
#pragma unroll
        for (int i = 0; i < 2; i++) {
            size_t gw = (size_t)(k0 + wRow[i]) * N + bn0 + wCol[i];
            cp16(smb + OFF_W + slot * W_PLANE + wS[i], Wh + gw);
        }
    };
    auto stsA = [&](int t, int slot, float4* ar) {
        const int k0 = t << 5;
        char* nb = sm + slot * A_PLANE;
#pragma unroll
        for (int i = 0; i < 4; i++) {
            float4 v = ar[i];
            float4 sc = *(const float4*)(g_scale + k0 + a_c[i]);
            float4 sh = *(const float4*)(g_shift + k0 + a_c[i]);
            v.x = fmaxf(v.x * sc.x + sh.x, 0.f);
            v.y = fmaxf(v.y * sc.y + sh.y, 0.f);
            v.z = fmaxf(v.z * sc.z + sh.z, 0.f);
            v.w = fmaxf(v.w * sc.w + sh.w, 0.f);
            cvt4h(v, nb + a_soff[i]);
        }
    };

    float4 ar[4];

    // ---- prologue: W0, W1 in flight; A0 converted into slot 0 ----
    issueW(0, 0); CP_COMMIT();
    if (1 < T) issueW(1, 1);
    CP_COMMIT();
#pragma unroll
    for (int i = 0; i < 4; i++)
        ar[i] = *(const float4*)(A + (size_t)(bm0 + a_row[i]) * K + a_c[i]);
    stsA(0, 0, ar);

    int wslot = 0;
    for (int t = 0; t < T; t++) {
        const int k0n = (t + 1) << 5;
        if (t + 1 < T) {
#pragma unroll
            for (int i = 0; i < 4; i++)
                ar[i] = *(const float4*)(A + (size_t)(bm0 + a_row[i]) * K + k0n + a_c[i]);
        }
        CP_WAIT(1);                 // W(t) landed (W(t+1) may be in flight)
        __syncthreads();            // publish W(t) + A slot written last iter
        if (t + 2 < T) {
            int ns = wslot + 2;
            if (ns >= 3) ns -= 3;   // correct mod-3 ring slot
            issueW(t + 2, ns);
        }
        CP_COMMIT();

        const uint32_t sA = smb + (t & 1) * A_PLANE;
        const uint32_t sW = smb + OFF_W + wslot * W_PLANE;
#pragma unroll
        for (int ks = 0; ks < 2; ks++) {
            uint32_t ah[4][4];
#pragma unroll
            for (int mt = 0; mt < 4; mt++)
                ldsm_x4(ah[mt], sA + a_off[mt] + ks * 32);
#pragma unroll
            for (int np = 0; np < 2; np++) {
                uint32_t bh[4];
                ldsm_x4_t(bh, sW + b_off[np] + ks * (16 * W_STR));
#pragma unroll
                for (int mt = 0; mt < 4; mt++)
#pragma unroll
                    for (int half = 0; half < 2; half++)
                        mma16816(acc[mt][np * 2 + half], ah[mt], bh[half * 2], bh[half * 2 + 1]);
            }
        }
        if (t + 1 < T) stsA(t + 1, (t + 1) & 1, ar);
        wslot = (wslot + 1 == 3) ? 0 : wslot + 1;
    }

    // epilogue
#pragma unroll
    for (int nt = 0; nt < 4; nt++) {
        int c0 = bn0 + warp_n + (nt >> 1) * 16 + (nt & 1) * 8 + (lane & 3) * 2;
        float b0 = bias[c0], b1 = bias[c0 + 1];
#pragma unroll
        for (int mt = 0; mt < 4; mt++) {
            int r0 = bm0 + warp_m + mt * 16 + (lane >> 2);
            float v0 = acc[mt][nt][0] + b0, v1 = acc[mt][nt][1] + b1;
            float v2 = acc[mt][nt][2] + b0, v3 = acc[mt][nt][3] + b1;
            if (OUT16) {
                __half* C16 = (__half*)Cout;
                __half2 h0 = __floats2half2_rn(v0, v1);
                __half2 h1 = __floats2half2_rn(v2, v3);
                *(__half2*)(C16 + (size_t)r0 * N + c0) = h0;
                *(__half2*)(C16 + (size_t)(r0 + 8) * N + c0) = h1;
            } else {
                float* C = (float*)Cout;
                float2 p0; p0.x = v0; p0.y = v1;
                float2 p1; p1.x = v2; p1.y = v3;
                *(float2*)(C + (size_t)r0 * N + c0) = p0;
                *(float2*)(C + (size_t)(r0 + 8) * N + c0) = p1;
            }
        }
    }
}

// ---------------- host orchestration ----------------
static const int G16_SMEM = 4 * 18944;            // 75776
static const int G32_SMEM = 2 * 10240 + 3 * 8704; // 46592

static __half *s_wh, *s_b16, *s_f0h, *s_f1h, *s_f2h;
static float *s_bufA;

template <bool CAT>
static void run_g16(const __half* left, const __half* right, const int* gidx,
                    int outRPB, int srcRPB, size_t woff,
                    const float* bias, float* C, int M, int N, int K) {
    dim3 grid(N / 128, M / 128);
    gemm16_kernel<CAT><<<grid, 256, G16_SMEM>>>(left, right, gidx, outRPB, srcRPB,
                                                s_wh + woff, bias, C, M, N, K);
}

template <bool OUT16>
static void run_g32(const float* A, size_t woff, const float* bias, void* C,
                    int M, int N, int K) {
    dim3 grid(N / 128, M / 128);
    gemm32_kernel<OUT16><<<grid, 256, G32_SMEM>>>(A, s_wh + woff, bias, C, M, N, K);
}

extern "C" void kernel_launch(void* const* d_in, const int* in_sizes, int n_in,
                              void* d_out, int out_size) {
    const float* f0 = (const float*)d_in[0];
    const float* f1 = (const float*)d_in[1];
    const float* f2 = (const float*)d_in[2];
    const float* up0_w1 = (const float*)d_in[3];
    const float* up0_b1 = (const float*)d_in[4];
    const float* up0_g  = (const float*)d_in[5];
    const float* up0_be = (const float*)d_in[6];
    const float* up0_w2 = (const float*)d_in[7];
    const float* up0_b2 = (const float*)d_in[8];
    const float* up1_w1 = (const float*)d_in[9];
    const float* up1_b1 = (const float*)d_in[10];
    const float* up1_g  = (const float*)d_in[11];
    const float* up1_be = (const float*)d_in[12];
    const float* up1_w2 = (const float*)d_in[13];
    const float* up1_b2 = (const float*)d_in[14];
    const float* skip0_w1 = (const float*)d_in[15];
    const float* skip0_b1 = (const float*)d_in[16];
    const float* skip0_g  = (const float*)d_in[17];
    const float* skip0_be = (const float*)d_in[18];
    const float* skip0_w2 = (const float*)d_in[19];
    const float* skip0_b2 = (const float*)d_in[20];
    const float* skip1_w1 = (const float*)d_in[21];
    const float* skip1_b1 = (const float*)d_in[22];
    const float* skip1_g  = (const float*)d_in[23];
    const float* skip1_be = (const float*)d_in[24];
    const float* skip1_w2 = (const float*)d_in[25];
    const float* skip1_b2 = (const float*)d_in[26];
    const int*   pool0 = (const int*)d_in[27];
    const int*   pool1 = (const int*)d_in[28];
    float* out = (float*)d_out;

    cudaGetSymbolAddress((void**)&s_bufA, g_bufA);
    cudaGetSymbolAddress((void**)&s_b16, g_b16);
    cudaGetSymbolAddress((void**)&s_f0h, g_f0h);
    cudaGetSymbolAddress((void**)&s_f1h, g_f1h);
    cudaGetSymbolAddress((void**)&s_f2h, g_f2h);
    cudaGetSymbolAddress((void**)&s_wh, g_wh);

    cudaFuncSetAttribute(gemm16_kernel<false>, cudaFuncAttributeMaxDynamicSharedMemorySize, G16_SMEM);
    cudaFuncSetAttribute(gemm16_kernel<true>,  cudaFuncAttributeMaxDynamicSharedMemorySize, G16_SMEM);
    cudaFuncSetAttribute(gemm32_kernel<false>, cudaFuncAttributeMaxDynamicSharedMemorySize, G32_SMEM);
    cudaFuncSetAttribute(gemm32_kernel<true>,  cudaFuncAttributeMaxDynamicSharedMemorySize, G32_SMEM);

    const int B = 4;
    const int N0 = 32768, N1 = 8192, N2 = 2048;
    const int C0 = 256, C1 = 512, C2 = 1024;
    const int M_u1 = B * N2, M_s1 = B * N1, M_s0 = B * N0;

    const size_t O_U1W1 = 0;
    const size_t O_U1W2 = 1048576;
    const size_t O_S1W1 = 1572864;
    const size_t O_S1W2 = 2621440;
    const size_t O_U0W1 = 3145728;
    const size_t O_U0W2 = 3407872;
    const size_t O_S0W1 = 3538944;
    const size_t O_S0W2 = 3801088;

    // ---- up1 MLP: f2h (8192,1024) -> 1024 -> 512 ----
    cvt_kernel<<<512, 256>>>(f2, s_f2h, (long long)M_u1 * C2 / 4);
    cvt_kernel<<<512, 256>>>(up1_w1, s_wh + O_U1W1, (long long)C2 * C2 / 4);
    zero_stats_kernel<<<4, 256>>>(1024);
    run_g16<false>(s_f2h, nullptr, nullptr, 1, 1, O_U1W1, up1_b1, s_bufA, M_u1, C2, C2);  // profiled
    cvt_kernel<<<512, 256>>>(up1_w2, s_wh + O_U1W2, (long long)C2 * C1 / 4);
    finalize_stats_kernel<<<4, 256>>>(up1_g, up1_be, C2, 1.0f / M_u1);
    run_g32<true>(s_bufA, O_U1W2, up1_b2, s_b16, M_u1, C1, C2);

    // ---- skip1 MLP: concat(f1h, gather(b16, pool1)) ----
    cvt_kernel<<<512, 256>>>(f1, s_f1h, (long long)M_s1 * C1 / 4);
    zero_stats_kernel<<<4, 256>>>(1024);
    cvt_kernel<<<512, 256>>>(skip1_w1, s_wh + O_S1W1, (long long)(2 * C1) * (2 * C1) / 4);
    cvt_kernel<<<512, 256>>>(skip1_w2, s_wh + O_S1W2, (long long)(2 * C1) * C1 / 4);
    run_g16<true>(s_f1h, s_b16, pool1, N1, N2, O_S1W1, skip1_b1, s_bufA, M_s1, 2 * C1, 2 * C1);
    finalize_stats_kernel<<<4, 256>>>(skip1_g, skip1_be, 2 * C1, 1.0f / M_s1);
    run_g32<true>(s_bufA, O_S1W2, skip1_b2, s_b16, M_s1, C1, 2 * C1);

    // ---- up0 MLP: b16 (32768,512) -> 512 -> 256 ----
    zero_stats_kernel<<<2, 256>>>(512);
    cvt_kernel<<<256, 256>>>(up0_w1, s_wh + O_U0W1, (long long)C1 * C1 / 4);
    cvt_kernel<<<256, 256>>>(up0_w2, s_wh + O_U0W2, (long long)C1 * C0 / 4);
    run_g16<false>(s_b16, nullptr, nullptr, 1, 1, O_U0W1, up0_b1, s_bufA, M_s1, C1, C1);
    finalize_stats_kernel<<<2, 256>>>(up0_g, up0_be, C1, 1.0f / M_s1);
    run_g32<true>(s_bufA, O_U0W2, up0_b2, s_b16, M_s1, C0, C1);

    // ---- skip0 MLP: concat(f0h, gather(b16, pool0)) -> out ----
    cvt_kernel<<<1024, 256>>>(f0, s_f0h, (long long)M_s0 * C0 / 4);
    zero_stats_kernel<<<2, 256>>>(512);
    cvt_kernel<<<256, 256>>>(skip0_w1, s_wh + O_S0W1, (long long)(2 * C0) * (2 * C0) / 4);
    cvt_kernel<<<256, 256>>>(skip0_w2, s_wh + O_S0W2, (long long)(2 * C0) * C0 / 4);
    run_g16<true>(s_f0h, s_b16, pool0, N0, N1, O_S0W1, skip0_b1, s_bufA, M_s0, 2 * C0, 2 * C0);
    finalize_stats_kernel<<<2, 256>>>(skip0_g, skip0_be, 2 * C0, 1.0f / M_s0);
    run_g32<false>(s_bufA, O_S0W2, skip0_b2, out, M_s0, C0, 2 * C0);
}